// round 16
// baseline (speedup 1.0000x reference)
#include <cuda_runtime.h>
#include <cuda_bf16.h>

#define TT 512
#define H 8
#define NSM 148
#define BLK 512
#define SEGS_PER_BLK (BLK / 16)

typedef unsigned long long u64;

__device__ __forceinline__ float tanhf_a(float x) {
    float y; asm("tanh.approx.f32 %0, %1;" : "=f"(y) : "f"(x)); return y;
}
__device__ __forceinline__ u64 pack2(float lo, float hi) {
    u64 r; asm("mov.b64 %0, {%1, %2};" : "=l"(r) : "f"(lo), "f"(hi)); return r;
}
__device__ __forceinline__ void unpack2(u64 v, float& lo, float& hi) {
    asm("mov.b64 {%0, %1}, %2;" : "=f"(lo), "=f"(hi) : "l"(v));
}
__device__ __forceinline__ u64 fma2(u64 a, u64 b, u64 c) {
    u64 r; asm("fma.rn.f32x2 %0, %1, %2, %3;" : "=l"(r) : "l"(a), "l"(b), "l"(c)); return r;
}
__device__ __forceinline__ u64 mul2(u64 a, u64 b) {
    u64 r; asm("mul.rn.f32x2 %0, %1, %2;" : "=l"(r) : "l"(a), "l"(b)); return r;
}
__device__ __forceinline__ float hsum2(u64 v) {
    float lo, hi; unpack2(v, lo, hi); return lo + hi;
}
__device__ __forceinline__ u64 d2u(double d) {
    return (u64)__double_as_longlong(d);
}

__global__ void __launch_bounds__(BLK, 1)
lstm2_kernel(const float* __restrict__ x,
             const float* __restrict__ W_ih1, const float* __restrict__ W_hh1,
             const float* __restrict__ b_ih1, const float* __restrict__ b_hh1,
             const float* __restrict__ W_ih2, const float* __restrict__ W_hh2,
             const float* __restrict__ b_ih2, const float* __restrict__ b_hh2,
             const float* __restrict__ W_fc,  const float* __restrict__ b_fc,
             float* __restrict__ out, int B)
{
    const int m     = threadIdx.x & 15;                 // lane within 16-lane segment
    const int gp    = m >> 3;                           // 0: gates (i,f); 1: gates (g,o)
    const int n     = m & 7;                            // hidden unit of this lane
    const int sg    = threadIdx.x >> 4;                 // segment index in block (0..31)
    const int seg   = blockIdx.x * SEGS_PER_BLK + sg;   // global segment id
    const bool active = (seg < B);
    const int batch = active ? seg : 0;                 // dummy segments replay batch 0
    const unsigned FULL = 0xffffffffu;
    const bool g0 = (gp == 0);

    // ping-pong broadcast buffers: [parity][segment][layer][unit]
    __shared__ __align__(16) float hbuf[2][SEGS_PER_BLK][2][8];

    // sigmoid(z) = 0.5*tanh(0.5*z)+0.5 -> fold 0.5 into sigmoid-gate rows;
    // tanh gate (g) scale 1. Row a = (i or g), row b = (f or o).
    const int ra = g0 ? n        : 16 + n;              // i-row or g-row
    const int rb = g0 ? 8 + n    : 24 + n;              // f-row or o-row
    const float sa = g0 ? 0.5f : 1.0f;                  // i:0.5  g:1.0
    const float sb = 0.5f;                              // f,o: 0.5

    // layer-1 x weights (scalar; applied post-hsum)
    const float wxa = W_ih1[ra] * sa;
    const float wxb = W_ih1[rb] * sb;

    // biases packed as (b, 0): seeds of the packed accumulator chains
    const u64 b1a = pack2((b_ih1[ra] + b_hh1[ra]) * sa, 0.0f);
    const u64 b1b = pack2((b_ih1[rb] + b_hh1[rb]) * sb, 0.0f);
    const u64 b2a = pack2((b_ih2[ra] + b_hh2[ra]) * sa, 0.0f);
    const u64 b2b = pack2((b_ih2[rb] + b_hh2[rb]) * sb, 0.0f);

    // weights, k-packed: 2 rows x 3 matrices x 4 pairs = 24 u64
    u64 w1a[4], w1b[4];        // W_hh1 rows ra, rb
    u64 w2ia[4], w2ib[4];      // W_ih2 rows ra, rb
    u64 w2ha[4], w2hb[4];      // W_hh2 rows ra, rb
#pragma unroll
    for (int p = 0; p < 4; ++p) {
        const int k0 = 2*p, k1 = 2*p + 1;
        w1a[p]  = pack2(W_hh1[ra*H + k0] * sa, W_hh1[ra*H + k1] * sa);
        w1b[p]  = pack2(W_hh1[rb*H + k0] * sb, W_hh1[rb*H + k1] * sb);
        w2ia[p] = pack2(W_ih2[ra*H + k0] * sa, W_ih2[ra*H + k1] * sa);
        w2ib[p] = pack2(W_ih2[rb*H + k0] * sb, W_ih2[rb*H + k1] * sb);
        w2ha[p] = pack2(W_hh2[ra*H + k0] * sa, W_hh2[ra*H + k1] * sa);
        w2hb[p] = pack2(W_hh2[rb*H + k0] * sb, W_hh2[rb*H + k1] * sb);
    }

    const u64 Z = pack2(0.0f, 0.0f);
    const u64 HALF2 = pack2(0.5f, 0.5f);
    u64 h1p[4], h2p[4];           // h1(t-1), h2(t-2) broadcasts (packed pairs)
#pragma unroll
    for (int p = 0; p < 4; ++p) { h1p[p] = Z; h2p[p] = Z; }
    u64 c12 = Z;                  // packed (c1, c2), kept redundantly in all lanes of unit n

    // One pipelined body: layer1(t) [uses h1p, xt] || layer2(t-1) [uses h1p, h2p]
    auto step = [&](float xt, int par) {
        // ---- 4 packed chains: L1 rows (4-deep), L2 rows (8-deep merged) ----
        u64 va = b1a, vb = b1b;
        u64 ua = b2a, ub = b2b;
#pragma unroll
        for (int p = 0; p < 4; ++p) {
            va = fma2(w1a[p],  h1p[p], va);
            vb = fma2(w1b[p],  h1p[p], vb);
            ua = fma2(w2ia[p], h1p[p], ua);
            ub = fma2(w2ib[p], h1p[p], ub);
        }
#pragma unroll
        for (int p = 0; p < 4; ++p) {
            ua = fma2(w2ha[p], h2p[p], ua);
            ub = fma2(w2hb[p], h2p[p], ub);
        }
        const float a1a = fmaf(wxa, xt, hsum2(va));
        const float a1b = fmaf(wxb, xt, hsum2(vb));
        const float a2a = hsum2(ua);
        const float a2b = hsum2(ub);

        // 4 gate tanh (this lane's 2 gates per layer)
        const float t1a = tanhf_a(a1a);
        const float t1b = tanhf_a(a1b);
        const float t2a = tanhf_a(a2a);
        const float t2b = tanhf_a(a2b);

        // exchange with partner lane (other gate-pair, same unit): bfly xor 8
        const float r1a = __shfl_xor_sync(FULL, t1a, 8, 16);
        const float r1b = __shfl_xor_sync(FULL, t1b, 8, 16);
        const float r2a = __shfl_xor_sync(FULL, t2a, 8, 16);
        const float r2b = __shfl_xor_sync(FULL, t2b, 8, 16);

        // gate role mapping (SELs): gp0 owns (i,f), receives (g,o); gp1 inverse
        const float i1 = g0 ? t1a : r1a;
        const float f1 = g0 ? t1b : r1b;
        const float gg1 = g0 ? r1a : t1a;
        const float o1 = g0 ? r1b : t1b;
        const float i2 = g0 ? t2a : r2a;
        const float f2 = g0 ? t2b : r2b;
        const float gg2 = g0 ? r2a : t2a;
        const float o2 = g0 ? r2b : t2b;

        // packed cross-layer tail (identical math to champion)
        const u64 Pi = pack2(i1, i2);
        const u64 Pf = pack2(f1, f2);
        const u64 Po = pack2(o1, o2);
        const u64 Pg = pack2(gg1, gg2);
        const u64 gi2v = fma2(Pi, HALF2, HALF2);
        const u64 gf2v = fma2(Pf, HALF2, HALF2);
        const u64 go2v = fma2(Po, HALF2, HALF2);

        c12 = fma2(gf2v, c12, mul2(gi2v, Pg));
        float cc1, cc2; unpack2(c12, cc1, cc2);
        const u64 Pc = pack2(tanhf_a(cc1), tanhf_a(cc2));
        const u64 h12 = mul2(go2v, Pc);
        float h1n, h2n; unpack2(h12, h1n, h2n);

        // ---- SMEM broadcast: 1 STS (gp0 writes h1, gp1 writes h2) + sync + 4 LDS.128
        hbuf[par][sg][gp][n] = g0 ? h1n : h2n;
        __syncwarp();
        const double2* pa = (const double2*)&hbuf[par][sg][0][0];
        const double2* pb = (const double2*)&hbuf[par][sg][1][0];
        const double2 a0 = pa[0], a1 = pa[1];
        const double2 b0 = pb[0], b1 = pb[1];
        h1p[0] = d2u(a0.x); h1p[1] = d2u(a0.y);
        h1p[2] = d2u(a1.x); h1p[3] = d2u(a1.y);
        h2p[0] = d2u(b0.x); h2p[1] = d2u(b0.y);
        h2p[2] = d2u(b1.x); h2p[3] = d2u(b1.y);
    };

    const float4* __restrict__ xr = (const float4*)(x + (size_t)batch * TT);
    float4 cur = xr[0];
    float4 nxt = xr[1];

    // prologue: first body computes layer1(0); its layer2(-1) output is junk
    step(cur.x, 0);
    {   // reset layer2 state (keep c1)
        float c1k, cj; unpack2(c12, c1k, cj);
        c12 = pack2(c1k, 0.0f);
    }
#pragma unroll
    for (int p = 0; p < 4; ++p) h2p[p] = Z;

    step(cur.y, 1); step(cur.z, 0); step(cur.w, 1);
    cur = nxt;

    for (int t4 = 1; t4 < TT/4; ++t4) {
        const int nidx = (t4 + 1 < TT/4) ? (t4 + 1) : t4;
        nxt = xr[nidx];
        step(cur.x, 0); step(cur.y, 1); step(cur.z, 0); step(cur.w, 1);
        cur = nxt;
    }

    // epilogue: one more body computes layer2(511); layer1(512) discarded
    step(0.0f, 0);

    // ---------- final FC (8 -> 4): h2p holds broadcast h2(511) ----------
    if (active && m < 4) {
        u64 acc = pack2(b_fc[m], 0.0f);
#pragma unroll
        for (int p = 0; p < 4; ++p) {
            const u64 w = pack2(W_fc[m*H + 2*p], W_fc[m*H + 2*p + 1]);
            acc = fma2(w, h2p[p], acc);
        }
        out[batch * 4 + m] = hsum2(acc);
    }
}

extern "C" void kernel_launch(void* const* d_in, const int* in_sizes, int n_in,
                              void* d_out, int out_size)
{
    const float* x     = (const float*)d_in[0];
    const float* W_ih1 = (const float*)d_in[1];
    const float* W_hh1 = (const float*)d_in[2];
    const float* b_ih1 = (const float*)d_in[3];
    const float* b_hh1 = (const float*)d_in[4];
    const float* W_ih2 = (const float*)d_in[5];
    const float* W_hh2 = (const float*)d_in[6];
    const float* b_ih2 = (const float*)d_in[7];
    const float* b_hh2 = (const float*)d_in[8];
    const float* W_fc  = (const float*)d_in[9];
    const float* b_fc  = (const float*)d_in[10];
    float* out = (float*)d_out;

    const int B = in_sizes[0] / TT;          // 4096
    // 148 blocks x 512 threads = 2368 warps = uniform 4 warps/SMSP on every SM;
    // 4736 segment slots >= 4096 batches (surplus run dummies)
    int blocks = NSM;
    const int min_blocks = (B * 16 + BLK - 1) / BLK;
    if (blocks < min_blocks) blocks = min_blocks;   // safety for other sizes

    lstm2_kernel<<<blocks, BLK>>>(x, W_ih1, W_hh1, b_ih1, b_hh1,
                                  W_ih2, W_hh2, b_ih2, b_hh2,
                                  W_fc, b_fc, out, B);
}